// round 3
// baseline (speedup 1.0000x reference)
#include <cuda_runtime.h>

// AttentionBlock fused gate kernel — persistent grid-stride, prefetch-pipelined.
// Inputs: xatt[B*L*C], xsaut[B*L*C], W_act[C], b_act[1], W_saut[C], b_saut[1], W2[1], b2[1]
// Output: out[B*L] fp32.  B=64, L=16384, C=64 -> n_pos = 1,048,576 (n_pairs = 524,288).
//
// 16 lanes per position-pair. Each iteration handles positions (p, p + n_pairs):
// 4 coalesced LDG.128 per thread. The loop prefetches the next iteration's 4
// loads before the current reduction, keeping ~8 independent LDG.128 in flight
// per thread in steady state.

#define NEG_SLOPE 0.3f

__global__ __launch_bounds__(256) void attn_gate_kernel(
    const float* __restrict__ xatt,
    const float* __restrict__ xsaut,
    const float* __restrict__ W_act,
    const float* __restrict__ b_act,
    const float* __restrict__ W_saut,
    const float* __restrict__ b_saut,
    const float* __restrict__ W2,
    const float* __restrict__ b2,
    float* __restrict__ out,
    int n_pairs)                      // n_pos / 2
{
    const int gtid    = blockIdx.x * blockDim.x + threadIdx.x;
    const int lane16  = gtid & 15;
    const int stride  = (gridDim.x * blockDim.x) >> 4;   // pairs per sweep
    int p = gtid >> 4;
    if (p >= n_pairs) return;

    const float4* __restrict__ xa4 = reinterpret_cast<const float4*>(xatt);
    const float4* __restrict__ xs4 = reinterpret_cast<const float4*>(xsaut);

    const float4 wa = __ldg(reinterpret_cast<const float4*>(W_act)  + lane16);
    const float4 ws = __ldg(reinterpret_cast<const float4*>(W_saut) + lane16);
    const float ba = __ldg(b_act);
    const float bs = __ldg(b_saut);
    const float w2 = __ldg(W2);
    const float bb = __ldg(b2);

    // Prime the pipeline
    float4 a0 = __ldg(xa4 + (size_t)p * 16 + lane16);
    float4 s0 = __ldg(xs4 + (size_t)p * 16 + lane16);
    float4 a1 = __ldg(xa4 + (size_t)(p + n_pairs) * 16 + lane16);
    float4 s1 = __ldg(xs4 + (size_t)(p + n_pairs) * 16 + lane16);

    while (true) {
        const int pn = p + stride;
        const bool more = (pn < n_pairs);
        // Prefetch next iteration (clamped to a valid index; result unused if !more)
        const int pf = more ? pn : p;
        float4 na0 = __ldg(xa4 + (size_t)pf * 16 + lane16);
        float4 ns0 = __ldg(xs4 + (size_t)pf * 16 + lane16);
        float4 na1 = __ldg(xa4 + (size_t)(pf + n_pairs) * 16 + lane16);
        float4 ns1 = __ldg(xs4 + (size_t)(pf + n_pairs) * 16 + lane16);

        float pa0 = a0.x * wa.x + a0.y * wa.y + a0.z * wa.z + a0.w * wa.w;
        float ps0 = s0.x * ws.x + s0.y * ws.y + s0.z * ws.z + s0.w * ws.w;
        float pa1 = a1.x * wa.x + a1.y * wa.y + a1.z * wa.z + a1.w * wa.w;
        float ps1 = s1.x * ws.x + s1.y * ws.y + s1.z * ws.z + s1.w * ws.w;

        #pragma unroll
        for (int off = 8; off > 0; off >>= 1) {
            pa0 += __shfl_xor_sync(0xFFFFFFFFu, pa0, off);
            ps0 += __shfl_xor_sync(0xFFFFFFFFu, ps0, off);
            pa1 += __shfl_xor_sync(0xFFFFFFFFu, pa1, off);
            ps1 += __shfl_xor_sync(0xFFFFFFFFu, ps1, off);
        }

        if (lane16 == 0) {
            {
                const float xs = ps0 + bs;
                float h = (pa0 + ba) + xs;
                h = (h >= 0.0f) ? h : NEG_SLOPE * h;
                const float z = h * w2 + bb;
                out[p] = xs / (1.0f + __expf(-z));
            }
            {
                const float xs = ps1 + bs;
                float h = (pa1 + ba) + xs;
                h = (h >= 0.0f) ? h : NEG_SLOPE * h;
                const float z = h * w2 + bb;
                out[p + n_pairs] = xs / (1.0f + __expf(-z));
            }
        }

        if (!more) break;
        p = pn;
        a0 = na0; s0 = ns0; a1 = na1; s1 = ns1;
    }
}

extern "C" void kernel_launch(void* const* d_in, const int* in_sizes, int n_in,
                              void* d_out, int out_size)
{
    const float* xatt   = (const float*)d_in[0];
    const float* xsaut  = (const float*)d_in[1];
    const float* W_act  = (const float*)d_in[2];
    const float* b_act  = (const float*)d_in[3];
    const float* W_saut = (const float*)d_in[4];
    const float* b_saut = (const float*)d_in[5];
    const float* W2     = (const float*)d_in[6];
    const float* b2     = (const float*)d_in[7];
    float* out = (float*)d_out;

    const int n_pairs = out_size / 2;        // 524,288
    const int threads = 256;
    const int blocks  = 152 * 8;             // persistent: GB300 has 152 SMs

    attn_gate_kernel<<<blocks, threads>>>(xatt, xsaut, W_act, b_act,
                                          W_saut, b_saut, W2, b2,
                                          out, n_pairs);
}

// round 4
// speedup vs baseline: 1.0251x; 1.0251x over previous
#include <cuda_runtime.h>

// AttentionBlock fused gate kernel — ILP=2 over ADJACENT positions.
// Inputs: xatt[B*L*C], xsaut[B*L*C], W_act[C], b_act[1], W_saut[C], b_saut[1], W2[1], b2[1]
// Output: out[B*L] fp32.  B=64, L=16384, C=64 -> n_pos = 1,048,576.
//
// 16 lanes handle positions (2k, 2k+1): each lane loads one float4 from each
// input row of both positions -> 4 independent LDG.128, and the 16-lane group
// touches 512B fully contiguous per tensor (1KB per warp per tensor).

#define NEG_SLOPE 0.3f

__global__ __launch_bounds__(256) void attn_gate_kernel(
    const float* __restrict__ xatt,
    const float* __restrict__ xsaut,
    const float* __restrict__ W_act,
    const float* __restrict__ b_act,
    const float* __restrict__ W_saut,
    const float* __restrict__ b_saut,
    const float* __restrict__ W2,
    const float* __restrict__ b2,
    float* __restrict__ out,
    int n_pairs)
{
    const int gtid   = blockIdx.x * blockDim.x + threadIdx.x;
    const int pair   = gtid >> 4;
    const int lane16 = gtid & 15;
    if (pair >= n_pairs) return;
    const int pos0 = pair * 2;

    const float4 wa = __ldg(reinterpret_cast<const float4*>(W_act)  + lane16);
    const float4 ws = __ldg(reinterpret_cast<const float4*>(W_saut) + lane16);

    const float4* __restrict__ xa4 = reinterpret_cast<const float4*>(xatt);
    const float4* __restrict__ xs4 = reinterpret_cast<const float4*>(xsaut);
    const size_t base = (size_t)pos0 * 16 + lane16;

    // Front-batch 4 independent global loads; per-tensor addresses are
    // base and base+16 (contiguous 512B for the 16-lane group).
    const float4 a0 = __ldg(xa4 + base);
    const float4 a1 = __ldg(xa4 + base + 16);
    const float4 s0 = __ldg(xs4 + base);
    const float4 s1 = __ldg(xs4 + base + 16);

    float pa0 = a0.x * wa.x + a0.y * wa.y + a0.z * wa.z + a0.w * wa.w;
    float ps0 = s0.x * ws.x + s0.y * ws.y + s0.z * ws.z + s0.w * ws.w;
    float pa1 = a1.x * wa.x + a1.y * wa.y + a1.z * wa.z + a1.w * wa.w;
    float ps1 = s1.x * ws.x + s1.y * ws.y + s1.z * ws.z + s1.w * ws.w;

    #pragma unroll
    for (int off = 8; off > 0; off >>= 1) {
        pa0 += __shfl_xor_sync(0xFFFFFFFFu, pa0, off);
        ps0 += __shfl_xor_sync(0xFFFFFFFFu, ps0, off);
        pa1 += __shfl_xor_sync(0xFFFFFFFFu, pa1, off);
        ps1 += __shfl_xor_sync(0xFFFFFFFFu, ps1, off);
    }

    if (lane16 == 0) {
        const float ba = __ldg(b_act);
        const float bs = __ldg(b_saut);
        const float w2 = __ldg(W2);
        const float bb = __ldg(b2);

        const float xs0 = ps0 + bs;
        float h0 = (pa0 + ba) + xs0;
        h0 = (h0 >= 0.0f) ? h0 : NEG_SLOPE * h0;
        const float z0 = h0 * w2 + bb;

        const float xs1 = ps1 + bs;
        float h1 = (pa1 + ba) + xs1;
        h1 = (h1 >= 0.0f) ? h1 : NEG_SLOPE * h1;
        const float z1 = h1 * w2 + bb;

        // Adjacent 8-byte store pair
        float2 o;
        o.x = xs0 / (1.0f + __expf(-z0));
        o.y = xs1 / (1.0f + __expf(-z1));
        reinterpret_cast<float2*>(out)[pair] = o;
    }
}

extern "C" void kernel_launch(void* const* d_in, const int* in_sizes, int n_in,
                              void* d_out, int out_size)
{
    const float* xatt   = (const float*)d_in[0];
    const float* xsaut  = (const float*)d_in[1];
    const float* W_act  = (const float*)d_in[2];
    const float* b_act  = (const float*)d_in[3];
    const float* W_saut = (const float*)d_in[4];
    const float* b_saut = (const float*)d_in[5];
    const float* W2     = (const float*)d_in[6];
    const float* b2     = (const float*)d_in[7];
    float* out = (float*)d_out;

    const int n_pairs = out_size / 2;        // 524,288
    const int threads = 256;
    const long long total_threads = (long long)n_pairs * 16;
    const int blocks = (int)((total_threads + threads - 1) / threads);

    attn_gate_kernel<<<blocks, threads>>>(xatt, xsaut, W_act, b_act,
                                          W_saut, b_saut, W2, b2,
                                          out, n_pairs);
}